// round 1
// baseline (speedup 1.0000x reference)
#include <cuda_runtime.h>
#include <cstddef>

// Problem constants
#define BATCH 2
#define TT    1024
#define DM    1024
#define NH    16
#define TD    5
#define DH    64
#define PCOLS (NH * TD)   // 80

// Scratch (no allocation allowed -> __device__ globals)
__device__ float g_P[BATCH * TT * PCOLS];    // sigmoid(x@Wp + bp), (B*T, 80)
__device__ float g_V[BATCH * TT * DM];       // x@Wv,  (B*T, 1024)
__device__ float g_CTX[BATCH * TT * DM];     // attn@V reassembled, (B*T, 1024)

// ---------------------------------------------------------------------------
// Generic fp32 SGEMM body: C[M,N] = A[M,K] @ B[K,N] (+bias, sigmoid if SIG).
// 128x128 block tile, BK=16, 256 threads, 8x8 per-thread microtile.
// M,K assumed multiples of 128/16; N guarded (for N=80 case).
// ---------------------------------------------------------------------------
template<int M, int N, int K, bool SIG>
__device__ __forceinline__ void sgemm_body(const float* __restrict__ A,
                                           const float* __restrict__ B,
                                           const float* __restrict__ bias,
                                           float* __restrict__ C)
{
    constexpr int BM = 128, BN = 128, BK = 16;
    __shared__ float As[BK][BM + 4];   // stored transposed: As[k][m]
    __shared__ float Bs[BK][BN + 4];

    const int tid = threadIdx.x;           // 0..255
    const int tx  = tid & 15;
    const int ty  = tid >> 4;
    const int bm  = blockIdx.y * BM;
    const int bn  = blockIdx.x * BN;

    float acc[8][8];
    #pragma unroll
    for (int i = 0; i < 8; i++)
        #pragma unroll
        for (int j = 0; j < 8; j++) acc[i][j] = 0.f;

    for (int k0 = 0; k0 < K; k0 += BK) {
        // Load A tile (128 x 16), store transposed.
        #pragma unroll
        for (int i = 0; i < 2; i++) {
            int f = tid + i * 256;             // 0..511
            int r = f >> 2;                    // 0..127
            int c = (f & 3) * 4;               // 0,4,8,12
            float4 v = *(const float4*)(A + (size_t)(bm + r) * K + k0 + c);
            As[c + 0][r] = v.x;
            As[c + 1][r] = v.y;
            As[c + 2][r] = v.z;
            As[c + 3][r] = v.w;
        }
        // Load B tile (16 x 128), N-guarded.
        #pragma unroll
        for (int i = 0; i < 2; i++) {
            int f = tid + i * 256;
            int r = f >> 5;                    // 0..15
            int c = (f & 31) * 4;              // 0..124
            float4 v;
            if (bn + c < N)
                v = *(const float4*)(B + (size_t)(k0 + r) * N + bn + c);
            else
                v = make_float4(0.f, 0.f, 0.f, 0.f);
            *(float4*)&Bs[r][c] = v;
        }
        __syncthreads();

        #pragma unroll
        for (int kk = 0; kk < BK; kk++) {
            float ra[8], rb[8];
            float4 t;
            t = *(const float4*)&As[kk][ty * 8 + 0];
            ra[0] = t.x; ra[1] = t.y; ra[2] = t.z; ra[3] = t.w;
            t = *(const float4*)&As[kk][ty * 8 + 4];
            ra[4] = t.x; ra[5] = t.y; ra[6] = t.z; ra[7] = t.w;
            t = *(const float4*)&Bs[kk][tx * 8 + 0];
            rb[0] = t.x; rb[1] = t.y; rb[2] = t.z; rb[3] = t.w;
            t = *(const float4*)&Bs[kk][tx * 8 + 4];
            rb[4] = t.x; rb[5] = t.y; rb[6] = t.z; rb[7] = t.w;
            #pragma unroll
            for (int i = 0; i < 8; i++)
                #pragma unroll
                for (int j = 0; j < 8; j++)
                    acc[i][j] = fmaf(ra[i], rb[j], acc[i][j]);
        }
        __syncthreads();
    }

    // Epilogue
    #pragma unroll
    for (int i = 0; i < 8; i++) {
        const int row = bm + ty * 8 + i;
        #pragma unroll
        for (int j = 0; j < 8; j += 4) {
            const int col = bn + tx * 8 + j;
            if (col < N) {
                float4 v = make_float4(acc[i][j], acc[i][j + 1],
                                       acc[i][j + 2], acc[i][j + 3]);
                if (SIG) {
                    v.x = 1.f / (1.f + __expf(-(v.x + bias[col + 0])));
                    v.y = 1.f / (1.f + __expf(-(v.y + bias[col + 1])));
                    v.z = 1.f / (1.f + __expf(-(v.z + bias[col + 2])));
                    v.w = 1.f / (1.f + __expf(-(v.w + bias[col + 3])));
                }
                *(float4*)(C + (size_t)row * N + col) = v;
            }
        }
    }
}

__global__ __launch_bounds__(256)
void gemm_p_kernel(const float* __restrict__ x, const float* __restrict__ Wp,
                   const float* __restrict__ bp)
{
    sgemm_body<BATCH * TT, PCOLS, DM, true>(x, Wp, bp, g_P);
}

__global__ __launch_bounds__(256)
void gemm_v_kernel(const float* __restrict__ x, const float* __restrict__ Wv)
{
    sgemm_body<BATCH * TT, DM, DM, false>(x, Wv, nullptr, g_V);
}

__global__ __launch_bounds__(256)
void gemm_o_kernel(const float* __restrict__ Wo, float* __restrict__ out)
{
    sgemm_body<BATCH * TT, DM, DM, false>(g_CTX, Wo, nullptr, out);
}

// ---------------------------------------------------------------------------
// Attention: per (b,h, 64-query block). 256 threads = 64 queries x 4 dim-splits.
// sim(q,k) = (1/5) * sum_d cumprod_d( pq*pk + (1-pq)(1-pk) ).
// sim in (0,1] -> exp without max-subtraction is safe; single-pass accumulate.
// Causal: k <= q.
// ---------------------------------------------------------------------------
__global__ __launch_bounds__(256)
void attn_kernel()
{
    __shared__ float  kp[64][TD];      // key paths tile
    __shared__ float4 Vt[64][16];      // V tile: 64 keys x 64 dims

    const int bh = blockIdx.y;
    const int b  = bh >> 4;
    const int h  = bh & 15;
    const int qb = blockIdx.x;
    const int tid = threadIdx.x;
    const int ql = tid >> 2;           // 0..63 local query
    const int ds = tid & 3;            // dim split: 16 floats each
    const int q  = qb * 64 + ql;

    // Query path params: a = fma(2p-1, pk, 1-p)
    float uq[TD], vq[TD];
    {
        const float* prow = g_P + (size_t)(b * TT + q) * PCOLS + h * TD;
        #pragma unroll
        for (int d = 0; d < TD; d++) {
            float p = prow[d];
            uq[d] = 2.f * p - 1.f;
            vq[d] = 1.f - p;
        }
    }

    float4 a0 = make_float4(0.f, 0.f, 0.f, 0.f);
    float4 a1 = a0, a2 = a0, a3 = a0;
    float denom = 0.f;

    for (int kb = 0; kb <= qb; kb++) {
        const int k0 = kb * 64;

        // stage key paths (64 x 5)
        for (int i = tid; i < 64 * TD; i += 256) {
            int r = i / TD, c = i - r * TD;
            kp[r][c] = g_P[(size_t)(b * TT + k0 + r) * PCOLS + h * TD + c];
        }
        // stage V tile (64 x 64 floats), coalesced
        #pragma unroll
        for (int i = 0; i < 4; i++) {
            int f = tid + i * 256;
            int r = f >> 4, c = f & 15;
            Vt[r][c] = *(const float4*)(g_V + (size_t)(b * TT + k0 + r) * DM
                                        + h * DH + c * 4);
        }
        __syncthreads();

        const int klim = (kb == qb) ? (ql + 1) : 64;
        for (int kk = 0; kk < klim; kk++) {
            float cp = 1.f, s = 0.f;
            #pragma unroll
            for (int d = 0; d < TD; d++) {
                float a = fmaf(uq[d], kp[kk][d], vq[d]);
                cp *= a;
                s  += cp;
            }
            float e = __expf(s * 0.2f);
            denom += e;
            float4 v0 = Vt[kk][ds * 4 + 0];
            float4 v1 = Vt[kk][ds * 4 + 1];
            float4 v2 = Vt[kk][ds * 4 + 2];
            float4 v3 = Vt[kk][ds * 4 + 3];
            a0.x = fmaf(e, v0.x, a0.x); a0.y = fmaf(e, v0.y, a0.y);
            a0.z = fmaf(e, v0.z, a0.z); a0.w = fmaf(e, v0.w, a0.w);
            a1.x = fmaf(e, v1.x, a1.x); a1.y = fmaf(e, v1.y, a1.y);
            a1.z = fmaf(e, v1.z, a1.z); a1.w = fmaf(e, v1.w, a1.w);
            a2.x = fmaf(e, v2.x, a2.x); a2.y = fmaf(e, v2.y, a2.y);
            a2.z = fmaf(e, v2.z, a2.z); a2.w = fmaf(e, v2.w, a2.w);
            a3.x = fmaf(e, v3.x, a3.x); a3.y = fmaf(e, v3.y, a3.y);
            a3.z = fmaf(e, v3.z, a3.z); a3.w = fmaf(e, v3.w, a3.w);
        }
        __syncthreads();
    }

    const float inv = 1.f / denom;
    float4* out = (float4*)(g_CTX + (size_t)(b * TT + q) * DM + h * DH + ds * 16);
    out[0] = make_float4(a0.x * inv, a0.y * inv, a0.z * inv, a0.w * inv);
    out[1] = make_float4(a1.x * inv, a1.y * inv, a1.z * inv, a1.w * inv);
    out[2] = make_float4(a2.x * inv, a2.y * inv, a2.z * inv, a2.w * inv);
    out[3] = make_float4(a3.x * inv, a3.y * inv, a3.z * inv, a3.w * inv);
}

// ---------------------------------------------------------------------------
// Launch
// ---------------------------------------------------------------------------
extern "C" void kernel_launch(void* const* d_in, const int* in_sizes, int n_in,
                              void* d_out, int out_size)
{
    const float* x  = (const float*)d_in[0];
    const float* Wp = (const float*)d_in[1];
    const float* bp = (const float*)d_in[2];
    const float* Wv = (const float*)d_in[3];
    const float* Wo = (const float*)d_in[4];
    float* out = (float*)d_out;

    const dim3 blk(256);

    // paths = sigmoid(x @ Wp + bp)   (2048 x 80)
    gemm_p_kernel<<<dim3(1, (BATCH * TT) / 128), blk>>>(x, Wp, bp);

    // V = x @ Wv                     (2048 x 1024)
    gemm_v_kernel<<<dim3(DM / 128, (BATCH * TT) / 128), blk>>>(x, Wv);

    // attention -> CTX
    attn_kernel<<<dim3(TT / 64, BATCH * NH), blk>>>();

    // out = CTX @ Wo                 (2048 x 1024)
    gemm_o_kernel<<<dim3(DM / 128, (BATCH * TT) / 128), blk>>>(Wo, out);
}

// round 5
// speedup vs baseline: 1.0434x; 1.0434x over previous
#include <cuda_runtime.h>
#include <cstddef>

// Problem constants
#define BATCH 2
#define TT    1024
#define DM    1024
#define NH    16
#define TD    5
#define DH    64
#define PCOLS (NH * TD)   // 80

// Scratch (no allocation allowed -> __device__ globals)
__device__ float g_P[BATCH * TT * PCOLS];    // sigmoid(x@Wp + bp), (B*T, 80)
__device__ float g_V[BATCH * TT * DM];       // x@Wv,  (B*T, 1024)
__device__ float g_CTX[BATCH * TT * DM];     // attn@V reassembled, (B*T, 1024)

// ---------------------------------------------------------------------------
// fp32 SGEMM body, double-buffered: C[*,N] = A[*,K] @ B[K,N] (+bias+sigmoid).
// 128x128 block tile, BK=16, 256 threads, 8x8 microtile. Shared memory is
// passed in (so one kernel can host two template instantiations).
// ---------------------------------------------------------------------------
#define BMg 128
#define BNg 128
#define BKg 16
#define SM_A(st, k, m) sA[((st) * BKg + (k)) * (BMg + 4) + (m)]
#define SM_B(st, k, n) sB[((st) * BKg + (k)) * (BNg + 4) + (n)]

template<int N, int K, bool SIG>
__device__ __forceinline__ void sgemm_body(const float* __restrict__ A,
                                           const float* __restrict__ B,
                                           const float* __restrict__ bias,
                                           float* __restrict__ C,
                                           int bm, int bn,
                                           float* sA, float* sB)
{
    const int tid = threadIdx.x;           // 0..255
    const int tx  = tid & 15;
    const int ty  = tid >> 4;

    // ---- initial tile -> stage 0
    #pragma unroll
    for (int i = 0; i < 2; i++) {
        int f = tid + i * 256, r = f >> 2, c = (f & 3) * 4;
        float4 v = *(const float4*)(A + (size_t)(bm + r) * K + c);
        SM_A(0, c + 0, r) = v.x; SM_A(0, c + 1, r) = v.y;
        SM_A(0, c + 2, r) = v.z; SM_A(0, c + 3, r) = v.w;
    }
    #pragma unroll
    for (int i = 0; i < 2; i++) {
        int f = tid + i * 256, r = f >> 5, c = (f & 31) * 4;
        float4 v = (bn + c < N) ? *(const float4*)(B + (size_t)r * N + bn + c)
                                : make_float4(0.f, 0.f, 0.f, 0.f);
        *(float4*)&SM_B(0, r, c) = v;
    }
    __syncthreads();

    float acc[8][8];
    #pragma unroll
    for (int i = 0; i < 8; i++)
        #pragma unroll
        for (int j = 0; j < 8; j++) acc[i][j] = 0.f;

    float4 pa[2], pb[2];
    int cur = 0;
    for (int k0 = 0; k0 < K; k0 += BKg) {
        const bool more = (k0 + BKg) < K;
        if (more) {   // prefetch next tile into registers
            #pragma unroll
            for (int i = 0; i < 2; i++) {
                int f = tid + i * 256, r = f >> 2, c = (f & 3) * 4;
                pa[i] = *(const float4*)(A + (size_t)(bm + r) * K + k0 + BKg + c);
            }
            #pragma unroll
            for (int i = 0; i < 2; i++) {
                int f = tid + i * 256, r = f >> 5, c = (f & 31) * 4;
                pb[i] = (bn + c < N)
                      ? *(const float4*)(B + (size_t)(k0 + BKg + r) * N + bn + c)
                      : make_float4(0.f, 0.f, 0.f, 0.f);
            }
        }
        // ---- compute on current stage
        #pragma unroll
        for (int kk = 0; kk < BKg; kk++) {
            float ra[8], rb[8];
            *(float4*)&ra[0] = *(const float4*)&SM_A(cur, kk, ty * 8);
            *(float4*)&ra[4] = *(const float4*)&SM_A(cur, kk, ty * 8 + 4);
            *(float4*)&rb[0] = *(const float4*)&SM_B(cur, kk, tx * 8);
            *(float4*)&rb[4] = *(const float4*)&SM_B(cur, kk, tx * 8 + 4);
            #pragma unroll
            for (int i = 0; i < 8; i++)
                #pragma unroll
                for (int j = 0; j < 8; j++)
                    acc[i][j] = fmaf(ra[i], rb[j], acc[i][j]);
        }
        if (more) {   // commit prefetched tile to the other stage
            int nxt = cur ^ 1;
            #pragma unroll
            for (int i = 0; i < 2; i++) {
                int f = tid + i * 256, r = f >> 2, c = (f & 3) * 4;
                SM_A(nxt, c + 0, r) = pa[i].x; SM_A(nxt, c + 1, r) = pa[i].y;
                SM_A(nxt, c + 2, r) = pa[i].z; SM_A(nxt, c + 3, r) = pa[i].w;
            }
            #pragma unroll
            for (int i = 0; i < 2; i++) {
                int f = tid + i * 256, r = f >> 5, c = (f & 31) * 4;
                *(float4*)&SM_B(nxt, r, c) = pb[i];
            }
            __syncthreads();
            cur = nxt;
        }
    }

    // ---- epilogue
    #pragma unroll
    for (int i = 0; i < 8; i++) {
        const int row = bm + ty * 8 + i;
        #pragma unroll
        for (int j = 0; j < 8; j += 4) {
            const int col = bn + tx * 8 + j;
            if (col < N) {
                float4 v = make_float4(acc[i][j], acc[i][j + 1],
                                       acc[i][j + 2], acc[i][j + 3]);
                if (SIG) {
                    v.x = 1.f / (1.f + __expf(-(v.x + bias[col + 0])));
                    v.y = 1.f / (1.f + __expf(-(v.y + bias[col + 1])));
                    v.z = 1.f / (1.f + __expf(-(v.z + bias[col + 2])));
                    v.w = 1.f / (1.f + __expf(-(v.w + bias[col + 3])));
                }
                *(float4*)(C + (size_t)row * N + col) = v;
            }
        }
    }
}

// Fused V + P GEMM: blocks 0..127 do V = x@Wv (16x8 tile grid),
// blocks 128..143 do P = sigmoid(x@Wp + bp). One wave on 148 SMs.
__global__ __launch_bounds__(256)
void gemm_vp_kernel(const float* __restrict__ x, const float* __restrict__ Wv,
                    const float* __restrict__ Wp, const float* __restrict__ bp)
{
    __shared__ float sA[2 * BKg * (BMg + 4)];
    __shared__ float sB[2 * BKg * (BNg + 4)];
    const int bid = blockIdx.x;
    if (bid < 128)
        sgemm_body<DM, DM, false>(x, Wv, nullptr, g_V,
                                  (bid >> 3) * 128, (bid & 7) * 128, sA, sB);
    else
        sgemm_body<PCOLS, DM, true>(x, Wp, bp, g_P,
                                    (bid - 128) * 128, 0, sA, sB);
}

__global__ __launch_bounds__(256)
void gemm_o_kernel(const float* __restrict__ Wo, float* __restrict__ out)
{
    __shared__ float sA[2 * BKg * (BMg + 4)];
    __shared__ float sB[2 * BKg * (BNg + 4)];
    sgemm_body<DM, DM, false>(g_CTX, Wo, nullptr, out,
                              blockIdx.y * 128, blockIdx.x * 128, sA, sB);
}

// ---------------------------------------------------------------------------
// Attention: per (b,h, 64-query block), 256 threads, two phases per key tile.
// Phase 1: 64x64 exp-sim matrix computed ONCE into smem (thread = (q, k-group)).
// Phase 2: PV accumulate from smem (thread = (q, dim-split)), uniform 64-k loop
// (masked entries are exactly 0, also feeding denom correctly).
// sim in (0,1] -> exp without max-subtraction is safe.
// ---------------------------------------------------------------------------
__global__ __launch_bounds__(256)
void attn_kernel()
{
    __shared__ float  kpT[TD][64];     // transposed key paths
    __shared__ float  Es[64][65];      // exp(sim), padded rows
    __shared__ float4 Vt[64][16];      // V tile: 64 keys x 64 dims

    const int bh = blockIdx.y;
    const int b  = bh >> 4;
    const int h  = bh & 15;
    const int qb = gridDim.x - 1 - blockIdx.x;   // heavy blocks first
    const int tid = threadIdx.x;

    // phase-1 mapping: q1 = tid & 63 (query), kg = tid >> 6 (16-key group)
    const int q1 = tid & 63;
    const int kg = tid >> 6;
    const int qg1 = qb * 64 + q1;
    // phase-2 mapping: ql = tid >> 2 (query), ds = tid & 3 (16-dim split)
    const int ql = tid >> 2;
    const int ds = tid & 3;

    // query path params for phase 1: agree = fma(2p-1, pk, 1-p)
    float uq[TD], vq[TD];
    {
        const float* prow = g_P + (size_t)(b * TT + qg1) * PCOLS + h * TD;
        #pragma unroll
        for (int d = 0; d < TD; d++) {
            float p = prow[d];
            uq[d] = 2.f * p - 1.f;
            vq[d] = 1.f - p;
        }
    }

    float4 a0 = make_float4(0.f, 0.f, 0.f, 0.f);
    float4 a1 = a0, a2 = a0, a3 = a0;
    float denom = 0.f;

    for (int kb = 0; kb <= qb; kb++) {
        const int k0 = kb * 64;

        // stage key paths transposed (5 x 64)
        for (int i = tid; i < TD * 64; i += 256) {
            int d = i >> 6, k = i & 63;
            kpT[d][k] = g_P[(size_t)(b * TT + k0 + k) * PCOLS + h * TD + d];
        }
        // stage V tile (64 keys x 64 dims), coalesced
        #pragma unroll
        for (int i = 0; i < 4; i++) {
            int f = tid + i * 256;
            int r = f >> 4, c = f & 15;
            Vt[r][c] = *(const float4*)(g_V + (size_t)(b * TT + k0 + r) * DM
                                        + h * DH + c * 4);
        }
        __syncthreads();

        // phase 1: each thread computes 16 (q,k) pairs once
        #pragma unroll
        for (int j = 0; j < 16; j++) {
            const int k = kg * 16 + j;
            float cp = 1.f, s = 0.f;
            #pragma unroll
            for (int d = 0; d < TD; d++) {
                float a = fmaf(uq[d], kpT[d][k], vq[d]);
                cp *= a;
                s  += cp;
            }
            float e = __expf(s * 0.2f);
            if (k0 + k > qg1) e = 0.f;          // causal mask
            Es[q1][k] = e;
        }
        __syncthreads();

        // phase 2: uniform PV accumulate
        #pragma unroll 8
        for (int kk = 0; kk < 64; kk++) {
            const float e = Es[ql][kk];
            denom += e;
            float4 v0 = Vt[kk][ds * 4 + 0];
            float4 v1 = Vt[kk][ds * 4 + 1];
            float4 v2 = Vt[kk][ds * 4 + 2];
            float4 v3 = Vt[kk][ds * 4 + 3];
            a0.x = fmaf(e, v0.x, a0.x); a0.y = fmaf(e, v0.y, a0.y);
            a0.z = fmaf(e, v0.z, a0.z); a0.w = fmaf(e, v0.w, a0.w);
            a1.x = fmaf(e, v1.x, a1.x); a1.y = fmaf(e, v1.y, a1.y);
            a1.z = fmaf(e, v1.z, a1.z); a1.w = fmaf(e, v1.w, a1.w);
            a2.x = fmaf(e, v2.x, a2.x); a2.y = fmaf(e, v2.y, a2.y);
            a2.z = fmaf(e, v2.z, a2.z); a2.w = fmaf(e, v2.w, a2.w);
            a3.x = fmaf(e, v3.x, a3.x); a3.y = fmaf(e, v3.y, a3.y);
            a3.z = fmaf(e, v3.z, a3.z); a3.w = fmaf(e, v3.w, a3.w);
        }
        __syncthreads();
    }

    const float inv = 1.f / denom;
    float4* outp = (float4*)(g_CTX + (size_t)(b * TT + qb * 64 + ql) * DM
                             + h * DH + ds * 16);
    outp[0] = make_float4(a0.x * inv, a0.y * inv, a0.z * inv, a0.w * inv);
    outp[1] = make_float4(a1.x * inv, a1.y * inv, a1.z * inv, a1.w * inv);
    outp[2] = make_float4(a2.x * inv, a2.y * inv, a2.z * inv, a2.w * inv);
    outp[3] = make_float4(a3.x * inv, a3.y * inv, a3.z * inv, a3.w * inv);
}

// ---------------------------------------------------------------------------
// Launch
// ---------------------------------------------------------------------------
extern "C" void kernel_launch(void* const* d_in, const int* in_sizes, int n_in,
                              void* d_out, int out_size)
{
    const float* x  = (const float*)d_in[0];
    const float* Wp = (const float*)d_in[1];
    const float* bp = (const float*)d_in[2];
    const float* Wv = (const float*)d_in[3];
    const float* Wo = (const float*)d_in[4];
    float* out = (float*)d_out;

    const dim3 blk(256);

    // V = x@Wv (128 blocks) fused with P = sigmoid(x@Wp+bp) (16 blocks)
    gemm_vp_kernel<<<144, blk>>>(x, Wv, Wp, bp);

    // attention -> CTX
    attn_kernel<<<dim3(TT / 64, BATCH * NH), blk>>>();

    // out = CTX @ Wo
    gemm_o_kernel<<<dim3(DM / 128, (BATCH * TT) / 128), blk>>>(Wo, out);
}

// round 6
// speedup vs baseline: 1.6250x; 1.5573x over previous
#include <cuda_runtime.h>
#include <cstddef>

// Problem constants
#define BATCH 2
#define TT    1024
#define DM    1024
#define NH    16
#define TD    5
#define DH    64
#define PCOLS (NH * TD)   // 80

// Scratch (no allocation allowed -> __device__ globals)
__device__ float g_P[BATCH * TT * PCOLS];    // sigmoid(x@Wp + bp), (B*T, 80)
__device__ float g_V[BATCH * TT * DM];       // x@Wv,  (B*T, 1024)
__device__ float g_CTX[BATCH * TT * DM];     // attn@V reassembled, (B*T, 1024)

// ---------------------------------------------------------------------------
// fp32 SGEMM body, double-buffered, 512 threads: C[*,N] = A[*,K] @ B[K,N].
// 128x128 block tile, BK=16, 8x4 per-thread microtile (16 warps/SM).
// ---------------------------------------------------------------------------
#define BMg 128
#define BNg 128
#define BKg 16
#define SM_A(st, k, m) sA[((st) * BKg + (k)) * (BMg + 4) + (m)]
#define SM_B(st, k, n) sB[((st) * BKg + (k)) * (BNg + 4) + (n)]

template<int N, int K, bool SIG>
__device__ __forceinline__ void sgemm_body(const float* __restrict__ A,
                                           const float* __restrict__ B,
                                           const float* __restrict__ bias,
                                           float* __restrict__ C,
                                           int bm, int bn,
                                           float* sA, float* sB)
{
    const int tid = threadIdx.x;           // 0..511
    const int tx  = tid & 31;              // col group (x4)
    const int ty  = tid >> 5;              // row group (x8)

    // loader indices (one float4 per thread per tile)
    const int ar = tid >> 2, ac = (tid & 3) * 4;   // A: 128 x 16
    const int br = tid >> 5, bc = (tid & 31) * 4;  // B: 16 x 128

    // ---- initial tile -> stage 0
    {
        float4 va = *(const float4*)(A + (size_t)(bm + ar) * K + ac);
        SM_A(0, ac + 0, ar) = va.x; SM_A(0, ac + 1, ar) = va.y;
        SM_A(0, ac + 2, ar) = va.z; SM_A(0, ac + 3, ar) = va.w;
        float4 vb = (bn + bc < N) ? *(const float4*)(B + (size_t)br * N + bn + bc)
                                  : make_float4(0.f, 0.f, 0.f, 0.f);
        *(float4*)&SM_B(0, br, bc) = vb;
    }
    __syncthreads();

    float acc[8][4];
    #pragma unroll
    for (int i = 0; i < 8; i++)
        #pragma unroll
        for (int j = 0; j < 4; j++) acc[i][j] = 0.f;

    float4 pa, pb;
    int cur = 0;
    for (int k0 = 0; k0 < K; k0 += BKg) {
        const bool more = (k0 + BKg) < K;
        if (more) {   // prefetch next tile into registers
            pa = *(const float4*)(A + (size_t)(bm + ar) * K + k0 + BKg + ac);
            pb = (bn + bc < N)
               ? *(const float4*)(B + (size_t)(k0 + BKg + br) * N + bn + bc)
               : make_float4(0.f, 0.f, 0.f, 0.f);
        }
        // ---- compute on current stage
        #pragma unroll
        for (int kk = 0; kk < BKg; kk++) {
            float ra[8], rb[4];
            *(float4*)&ra[0] = *(const float4*)&SM_A(cur, kk, ty * 8);
            *(float4*)&ra[4] = *(const float4*)&SM_A(cur, kk, ty * 8 + 4);
            *(float4*)&rb[0] = *(const float4*)&SM_B(cur, kk, tx * 4);
            #pragma unroll
            for (int i = 0; i < 8; i++)
                #pragma unroll
                for (int j = 0; j < 4; j++)
                    acc[i][j] = fmaf(ra[i], rb[j], acc[i][j]);
        }
        if (more) {   // commit prefetched tile to the other stage
            int nxt = cur ^ 1;
            SM_A(nxt, ac + 0, ar) = pa.x; SM_A(nxt, ac + 1, ar) = pa.y;
            SM_A(nxt, ac + 2, ar) = pa.z; SM_A(nxt, ac + 3, ar) = pa.w;
            *(float4*)&SM_B(nxt, br, bc) = pb;
            __syncthreads();
            cur = nxt;
        }
    }

    // ---- epilogue
    const int col = bn + tx * 4;
    if (col < N) {
        #pragma unroll
        for (int i = 0; i < 8; i++) {
            const int row = bm + ty * 8 + i;
            float4 v = make_float4(acc[i][0], acc[i][1], acc[i][2], acc[i][3]);
            if (SIG) {
                v.x = 1.f / (1.f + __expf(-(v.x + bias[col + 0])));
                v.y = 1.f / (1.f + __expf(-(v.y + bias[col + 1])));
                v.z = 1.f / (1.f + __expf(-(v.z + bias[col + 2])));
                v.w = 1.f / (1.f + __expf(-(v.w + bias[col + 3])));
            }
            *(float4*)(C + (size_t)row * N + col) = v;
        }
    }
}

// Fused V + P GEMM: blocks 0..127 do V = x@Wv, blocks 128..143 do
// P = sigmoid(x@Wp + bp). One wave on 148 SMs.
__global__ __launch_bounds__(512)
void gemm_vp_kernel(const float* __restrict__ x, const float* __restrict__ Wv,
                    const float* __restrict__ Wp, const float* __restrict__ bp)
{
    __shared__ float sA[2 * BKg * (BMg + 4)];
    __shared__ float sB[2 * BKg * (BNg + 4)];
    const int bid = blockIdx.x;
    if (bid < 128)
        sgemm_body<DM, DM, false>(x, Wv, nullptr, g_V,
                                  (bid >> 3) * 128, (bid & 7) * 128, sA, sB);
    else
        sgemm_body<PCOLS, DM, true>(x, Wp, bp, g_P,
                                    (bid - 128) * 128, 0, sA, sB);
}

__global__ __launch_bounds__(512)
void gemm_o_kernel(const float* __restrict__ Wo, float* __restrict__ out)
{
    __shared__ float sA[2 * BKg * (BMg + 4)];
    __shared__ float sB[2 * BKg * (BNg + 4)];
    sgemm_body<DM, DM, false>(g_CTX, Wo, nullptr, out,
                              blockIdx.y * 128, blockIdx.x * 128, sA, sB);
}

// ---------------------------------------------------------------------------
// Attention: per (b,h, 64-query block), 256 threads, ~19.7KB smem -> 2 CTAs/SM.
// Phase 1: 64x64 exp-sim computed once into smem, TRANSPOSED EsT[k][q].
// Phase 2: 2-way k-split; thread tile = 2 queries x 16 dims; V rows read by
// LDG (L1-resident). k-split partials reduced once per block at the end.
// sim in (0,1] -> exp without max-subtraction is safe. Masked entries are 0.
// ---------------------------------------------------------------------------
#define EST_STRIDE 66
#define RED_STRIDE 36

__global__ __launch_bounds__(256)
void attn_kernel()
{
    __shared__ float kpT[TD][64];          // transposed key paths
    __shared__ float buf[128 * RED_STRIDE]; // EsT[64][66] (4224 fl) / red[128][36]

    const int bh = blockIdx.y;
    const int b  = bh >> 4;
    const int h  = bh & 15;
    const int qb = gridDim.x - 1 - blockIdx.x;   // heavy blocks first
    const int tid = threadIdx.x;

    // phase-1 mapping: q1 = query, kg = 16-key group
    const int q1 = tid & 63;
    const int kg = tid >> 6;
    const int qg1 = qb * 64 + q1;
    // phase-2 mapping: ks = k half, qg = 2-query group, ds = 16-dim split
    const int ks   = tid >> 7;         // 0..1
    const int slot = tid & 127;
    const int qg   = slot >> 2;        // 0..31
    const int ds   = slot & 3;         // 0..3

    // query path params for phase 1: agree = fma(2p-1, pk, 1-p)
    float uq[TD], vq[TD];
    {
        const float* prow = g_P + (size_t)(b * TT + qg1) * PCOLS + h * TD;
        #pragma unroll
        for (int d = 0; d < TD; d++) {
            float p = prow[d];
            uq[d] = 2.f * p - 1.f;
            vq[d] = 1.f - p;
        }
    }

    float4 accA[4], accB[4];
    #pragma unroll
    for (int i = 0; i < 4; i++) {
        accA[i] = make_float4(0.f, 0.f, 0.f, 0.f);
        accB[i] = make_float4(0.f, 0.f, 0.f, 0.f);
    }
    float denA = 0.f, denB = 0.f;

    for (int kb = 0; kb <= qb; kb++) {
        const int k0 = kb * 64;

        // stage key paths transposed (5 x 64)
        for (int i = tid; i < TD * 64; i += 256) {
            int d = i >> 6, k = i & 63;
            kpT[d][k] = g_P[(size_t)(b * TT + k0 + k) * PCOLS + h * TD + d];
        }
        __syncthreads();

        // phase 1: each thread computes 16 (q,k) pairs once -> EsT[k][q]
        #pragma unroll
        for (int j = 0; j < 16; j++) {
            const int k = kg * 16 + j;
            float cp = 1.f, s = 0.f;
            #pragma unroll
            for (int d = 0; d < TD; d++) {
                float a = fmaf(uq[d], kpT[d][k], vq[d]);
                cp *= a;
                s  += cp;
            }
            float e = __expf(s * 0.2f);
            if (k0 + k > qg1) e = 0.f;          // causal mask
            buf[k * EST_STRIDE + q1] = e;
        }
        __syncthreads();

        // phase 2: this thread's k half, 2 queries x 16 dims, V via LDG
        const float* vbase = g_V + (size_t)(b * TT + k0 + ks * 32) * DM
                             + h * DH + ds * 16;
        #pragma unroll 4
        for (int kk2 = 0; kk2 < 32; kk2++) {
            const int kk = ks * 32 + kk2;
            const float2 e2 = *(const float2*)&buf[kk * EST_STRIDE + qg * 2];
            const float4* vr = (const float4*)(vbase + (size_t)kk2 * DM);
            float4 v0 = vr[0], v1 = vr[1], v2 = vr[2], v3 = vr[3];
            denA += e2.x; denB += e2.y;
            accA[0].x = fmaf(e2.x, v0.x, accA[0].x); accA[0].y = fmaf(e2.x, v0.y, accA[0].y);
            accA[0].z = fmaf(e2.x, v0.z, accA[0].z); accA[0].w = fmaf(e2.x, v0.w, accA[0].w);
            accA[1].x = fmaf(e2.x, v1.x, accA[1].x); accA[1].y = fmaf(e2.x, v1.y, accA[1].y);
            accA[1].z = fmaf(e2.x, v1.z, accA[1].z); accA[1].w = fmaf(e2.x, v1.w, accA[1].w);
            accA[2].x = fmaf(e2.x, v2.x, accA[2].x); accA[2].y = fmaf(e2.x, v2.y, accA[2].y);
            accA[2].z = fmaf(e2.x, v2.z, accA[2].z); accA[2].w = fmaf(e2.x, v2.w, accA[2].w);
            accA[3].x = fmaf(e2.x, v3.x, accA[3].x); accA[3].y = fmaf(e2.x, v3.y, accA[3].y);
            accA[3].z = fmaf(e2.x, v3.z, accA[3].z); accA[3].w = fmaf(e2.x, v3.w, accA[3].w);
            accB[0].x = fmaf(e2.y, v0.x, accB[0].x); accB[0].y = fmaf(e2.y, v0.y, accB[0].y);
            accB[0].z = fmaf(e2.y, v0.z, accB[0].z); accB[0].w = fmaf(e2.y, v0.w, accB[0].w);
            accB[1].x = fmaf(e2.y, v1.x, accB[1].x); accB[1].y = fmaf(e2.y, v1.y, accB[1].y);
            accB[1].z = fmaf(e2.y, v1.z, accB[1].z); accB[1].w = fmaf(e2.y, v1.w, accB[1].w);
            accB[2].x = fmaf(e2.y, v2.x, accB[2].x); accB[2].y = fmaf(e2.y, v2.y, accB[2].y);
            accB[2].z = fmaf(e2.y, v2.z, accB[2].z); accB[2].w = fmaf(e2.y, v2.w, accB[2].w);
            accB[3].x = fmaf(e2.y, v3.x, accB[3].x); accB[3].y = fmaf(e2.y, v3.y, accB[3].y);
            accB[3].z = fmaf(e2.y, v3.z, accB[3].z); accB[3].w = fmaf(e2.y, v3.w, accB[3].w);
        }
        __syncthreads();   // EsT consumed; safe for next tile (or reduction)
    }

    // ---- k-split reduction (once per block), reusing buf as scratch
    if (ks == 1) {
        float4* r = (float4*)&buf[slot * RED_STRIDE];
        r[0] = accA[0]; r[1] = accA[1]; r[2] = accA[2]; r[3] = accA[3];
        r[4] = accB[0]; r[5] = accB[1]; r[6] = accB[2]; r[7] = accB[3];
        buf[slot * RED_STRIDE + 32] = denA;
        buf[slot * RED_STRIDE + 33] = denB;
    }
    __syncthreads();
    if (ks == 0) {
        const float4* r = (const float4*)&buf[slot * RED_STRIDE];
        #pragma unroll
        for (int i = 0; i < 4; i++) {
            float4 ra = r[i], rb2 = r[4 + i];
            accA[i].x += ra.x;  accA[i].y += ra.y;  accA[i].z += ra.z;  accA[i].w += ra.w;
            accB[i].x += rb2.x; accB[i].y += rb2.y; accB[i].z += rb2.z; accB[i].w += rb2.w;
        }
        denA += buf[slot * RED_STRIDE + 32];
        denB += buf[slot * RED_STRIDE + 33];

        const float invA = 1.f / denA;
        const float invB = 1.f / denB;
        const int q = qb * 64 + qg * 2;
        float4* o0 = (float4*)(g_CTX + (size_t)(b * TT + q) * DM + h * DH + ds * 16);
        float4* o1 = (float4*)(g_CTX + (size_t)(b * TT + q + 1) * DM + h * DH + ds * 16);
        #pragma unroll
        for (int i = 0; i < 4; i++) {
            o0[i] = make_float4(accA[i].x * invA, accA[i].y * invA,
                                accA[i].z * invA, accA[i].w * invA);
            o1[i] = make_float4(accB[i].x * invB, accB[i].y * invB,
                                accB[i].z * invB, accB[i].w * invB);
        }
    }
}

// ---------------------------------------------------------------------------
// Launch
// ---------------------------------------------------------------------------
extern "C" void kernel_launch(void* const* d_in, const int* in_sizes, int n_in,
                              void* d_out, int out_size)
{
    const float* x  = (const float*)d_in[0];
    const float* Wp = (const float*)d_in[1];
    const float* bp = (const float*)d_in[2];
    const float* Wv = (const float*)d_in[3];
    const float* Wo = (const float*)d_in[4];
    float* out = (float*)d_out;

    // V = x@Wv (128 blocks) fused with P = sigmoid(x@Wp+bp) (16 blocks)
    gemm_vp_kernel<<<144, 512>>>(x, Wv, Wp, bp);

    // attention -> CTX
    attn_kernel<<<dim3(TT / 64, BATCH * NH), 256>>>();

    // out = CTX @ Wo
    gemm_o_kernel<<<dim3(DM / 128, (BATCH * TT) / 128), 512>>>(Wo, out);
}

// round 7
// speedup vs baseline: 2.4871x; 1.5305x over previous
#include <cuda_runtime.h>
#include <cstddef>
#include <cstdint>

// Problem constants
#define BATCH 2
#define TT    1024
#define DM    1024
#define NH    16
#define TD    5
#define DH    64
#define PCOLS (NH * TD)   // 80

// Scratch (no allocation allowed -> __device__ globals)
__device__ float g_P[BATCH * TT * PCOLS];    // sigmoid(x@Wp + bp), (B*T, 80)
__device__ float g_V[BATCH * TT * DM];       // x@Wv,  (B*T, 1024)
__device__ float g_CTX[BATCH * TT * DM];     // attn@V reassembled, (B*T, 1024)

// ---------------------------------------------------------------------------
// tf32 helpers
// ---------------------------------------------------------------------------
__device__ __forceinline__ uint32_t f2tf32(float x) {
    uint32_t r;
    asm("cvt.rna.tf32.f32 %0, %1;" : "=r"(r) : "f"(x));
    return r;
}

__device__ __forceinline__ void mma_tf32(float4& c, const uint32_t a[4],
                                         const uint32_t b[2]) {
    asm volatile(
        "mma.sync.aligned.m16n8k8.row.col.f32.tf32.tf32.f32 "
        "{%0,%1,%2,%3}, {%4,%5,%6,%7}, {%8,%9}, {%0,%1,%2,%3};"
        : "+f"(c.x), "+f"(c.y), "+f"(c.z), "+f"(c.w)
        : "r"(a[0]), "r"(a[1]), "r"(a[2]), "r"(a[3]), "r"(b[0]), "r"(b[1]));
}

// ---------------------------------------------------------------------------
// tf32 tensor-core GEMM: C[*,N] = A[*,K] @ B[K,N] (+bias+sigmoid if SIG).
// 128x128 block tile, BK=16, 256 threads = 8 warps (4m x 2n), warp tile 32x64.
// Fragments built from smem with the documented m16n8k8 thread mapping:
//   g = lane>>2 (0..7), t = lane&3 (0..3)
//   A: a0=A[m+g][k+t]  a1=A[m+g+8][k+t]  a2=A[m+g][k+t+4]  a3=A[m+g+8][k+t+4]
//   B: b0=B[k+t][n+g]  b1=B[k+t+4][n+g]
//   C: (row g, col 2t)=c.x  (g,2t+1)=c.y  (g+8,2t)=c.z  (g+8,2t+1)=c.w
// smem row pad = 8 floats (stride 136 -> 8-bank row skew, conflict-free frags).
// ---------------------------------------------------------------------------
#define BKt 16
#define TPAD 136
#define TS_A(st, k, m) sA[((st) * BKt + (k)) * TPAD + (m)]
#define TS_B(st, k, n) sB[((st) * BKt + (k)) * TPAD + (n)]

template<int N, int K, bool SIG>
__device__ __forceinline__ void tgemm_body(const float* __restrict__ A,
                                           const float* __restrict__ B,
                                           const float* __restrict__ bias,
                                           float* __restrict__ C,
                                           int bm, int bn,
                                           uint32_t* sA, uint32_t* sB)
{
    const int tid  = threadIdx.x;          // 0..255
    const int lane = tid & 31;
    const int wid  = tid >> 5;             // 0..7
    const int g    = lane >> 2;
    const int t    = lane & 3;
    const int wm   = (wid >> 1) * 32;      // warp m offset
    const int wn   = (wid & 1) * 64;       // warp n offset

    // loader indices: 2 float4 per thread per tile
    // A tile: 128 rows x 16 cols ; B tile: 16 rows x 128 cols
    #define LD_TILE(st, koff)                                                  \
    {                                                                          \
        _Pragma("unroll")                                                      \
        for (int i = 0; i < 2; i++) {                                          \
            int f = tid + i * 256, r = f >> 2, c = (f & 3) * 4;                \
            float4 v = *(const float4*)(A + (size_t)(bm + r) * K + (koff) + c);\
            TS_A(st, c + 0, r) = f2tf32(v.x);                                  \
            TS_A(st, c + 1, r) = f2tf32(v.y);                                  \
            TS_A(st, c + 2, r) = f2tf32(v.z);                                  \
            TS_A(st, c + 3, r) = f2tf32(v.w);                                  \
        }                                                                      \
        _Pragma("unroll")                                                      \
        for (int i = 0; i < 2; i++) {                                          \
            int f = tid + i * 256, r = f >> 5, c = (f & 31) * 4;               \
            float4 v = (bn + c < N)                                            \
                ? *(const float4*)(B + (size_t)((koff) + r) * N + bn + c)      \
                : make_float4(0.f, 0.f, 0.f, 0.f);                             \
            TS_B(st, r, c + 0) = f2tf32(v.x);                                  \
            TS_B(st, r, c + 1) = f2tf32(v.y);                                  \
            TS_B(st, r, c + 2) = f2tf32(v.z);                                  \
            TS_B(st, r, c + 3) = f2tf32(v.w);                                  \
        }                                                                      \
    }

    LD_TILE(0, 0)
    __syncthreads();

    float4 acc[2][8];
    #pragma unroll
    for (int mi = 0; mi < 2; mi++)
        #pragma unroll
        for (int ni = 0; ni < 8; ni++)
            acc[mi][ni] = make_float4(0.f, 0.f, 0.f, 0.f);

    float4 pa[2], pb[2];
    int cur = 0;
    for (int k0 = 0; k0 < K; k0 += BKt) {
        const bool more = (k0 + BKt) < K;
        if (more) {   // prefetch next tile into registers (raw fp32)
            #pragma unroll
            for (int i = 0; i < 2; i++) {
                int f = tid + i * 256, r = f >> 2, c = (f & 3) * 4;
                pa[i] = *(const float4*)(A + (size_t)(bm + r) * K + k0 + BKt + c);
            }
            #pragma unroll
            for (int i = 0; i < 2; i++) {
                int f = tid + i * 256, r = f >> 5, c = (f & 31) * 4;
                pb[i] = (bn + c < N)
                      ? *(const float4*)(B + (size_t)(k0 + BKt + r) * N + bn + c)
                      : make_float4(0.f, 0.f, 0.f, 0.f);
            }
        }
        // ---- compute on current stage: 2 k8 sub-steps
        #pragma unroll
        for (int s = 0; s < 2; s++) {
            const int kb = s * 8;
            uint32_t af[2][4], bf[8][2];
            #pragma unroll
            for (int mi = 0; mi < 2; mi++) {
                const int m0 = wm + mi * 16;
                af[mi][0] = TS_A(cur, kb + t,     m0 + g);
                af[mi][1] = TS_A(cur, kb + t,     m0 + g + 8);
                af[mi][2] = TS_A(cur, kb + t + 4, m0 + g);
                af[mi][3] = TS_A(cur, kb + t + 4, m0 + g + 8);
            }
            #pragma unroll
            for (int ni = 0; ni < 8; ni++) {
                const int n0 = wn + ni * 8;
                bf[ni][0] = TS_B(cur, kb + t,     n0 + g);
                bf[ni][1] = TS_B(cur, kb + t + 4, n0 + g);
            }
            #pragma unroll
            for (int mi = 0; mi < 2; mi++)
                #pragma unroll
                for (int ni = 0; ni < 8; ni++)
                    mma_tf32(acc[mi][ni], af[mi], bf[ni]);
        }
        if (more) {   // commit prefetched tile to the other stage
            int nxt = cur ^ 1;
            #pragma unroll
            for (int i = 0; i < 2; i++) {
                int f = tid + i * 256, r = f >> 2, c = (f & 3) * 4;
                TS_A(nxt, c + 0, r) = f2tf32(pa[i].x);
                TS_A(nxt, c + 1, r) = f2tf32(pa[i].y);
                TS_A(nxt, c + 2, r) = f2tf32(pa[i].z);
                TS_A(nxt, c + 3, r) = f2tf32(pa[i].w);
            }
            #pragma unroll
            for (int i = 0; i < 2; i++) {
                int f = tid + i * 256, r = f >> 5, c = (f & 31) * 4;
                TS_B(nxt, r, c + 0) = f2tf32(pb[i].x);
                TS_B(nxt, r, c + 1) = f2tf32(pb[i].y);
                TS_B(nxt, r, c + 2) = f2tf32(pb[i].z);
                TS_B(nxt, r, c + 3) = f2tf32(pb[i].w);
            }
            __syncthreads();
            cur = nxt;
        }
    }

    // ---- epilogue from fragments (float2 stores)
    #pragma unroll
    for (int mi = 0; mi < 2; mi++) {
        const int r0 = bm + wm + mi * 16 + g;
        #pragma unroll
        for (int ni = 0; ni < 8; ni++) {
            const int col = bn + wn + ni * 8 + 2 * t;
            if (col < N) {
                float2 lo = make_float2(acc[mi][ni].x, acc[mi][ni].y);
                float2 hi = make_float2(acc[mi][ni].z, acc[mi][ni].w);
                if (SIG) {
                    lo.x = 1.f / (1.f + __expf(-(lo.x + bias[col + 0])));
                    lo.y = 1.f / (1.f + __expf(-(lo.y + bias[col + 1])));
                    hi.x = 1.f / (1.f + __expf(-(hi.x + bias[col + 0])));
                    hi.y = 1.f / (1.f + __expf(-(hi.y + bias[col + 1])));
                }
                *(float2*)(C + (size_t)r0 * N + col)       = lo;
                *(float2*)(C + (size_t)(r0 + 8) * N + col) = hi;
            }
        }
    }
    #undef LD_TILE
}

// Fused V + P GEMM: blocks 0..127 do V = x@Wv, blocks 128..143 do
// P = sigmoid(x@Wp + bp). One wave on 148 SMs.
__global__ __launch_bounds__(256)
void gemm_vp_kernel(const float* __restrict__ x, const float* __restrict__ Wv,
                    const float* __restrict__ Wp, const float* __restrict__ bp)
{
    __shared__ uint32_t sA[2 * BKt * TPAD];
    __shared__ uint32_t sB[2 * BKt * TPAD];
    const int bid = blockIdx.x;
    if (bid < 128)
        tgemm_body<DM, DM, false>(x, Wv, nullptr, g_V,
                                  (bid >> 3) * 128, (bid & 7) * 128, sA, sB);
    else
        tgemm_body<PCOLS, DM, true>(x, Wp, bp, g_P,
                                    (bid - 128) * 128, 0, sA, sB);
}

__global__ __launch_bounds__(256)
void gemm_o_kernel(const float* __restrict__ Wo, float* __restrict__ out)
{
    __shared__ uint32_t sA[2 * BKt * TPAD];
    __shared__ uint32_t sB[2 * BKt * TPAD];
    tgemm_body<DM, DM, false>(g_CTX, Wo, nullptr, out,
                              blockIdx.y * 128, blockIdx.x * 128, sA, sB);
}

// ---------------------------------------------------------------------------
// Attention: per (b,h, 64-query block), 256 threads, ~19.7KB smem -> 2 CTAs/SM.
// Phase 1: 64x64 exp-sim computed once into smem, TRANSPOSED EsT[k][q].
// Phase 2: 2-way k-split; thread tile = 2 queries x 16 dims; V rows read by
// LDG (L1-resident). k-split partials reduced once per block at the end.
// sim in (0,1] -> exp without max-subtraction is safe. Masked entries are 0.
// ---------------------------------------------------------------------------
#define EST_STRIDE 66
#define RED_STRIDE 36

__global__ __launch_bounds__(256)
void attn_kernel()
{
    __shared__ float kpT[TD][64];          // transposed key paths
    __shared__ float buf[128 * RED_STRIDE]; // EsT[64][66] (4224 fl) / red[128][36]

    const int bh = blockIdx.y;
    const int b  = bh >> 4;
    const int h  = bh & 15;
    const int qb = gridDim.x - 1 - blockIdx.x;   // heavy blocks first
    const int tid = threadIdx.x;

    // phase-1 mapping: q1 = query, kg = 16-key group
    const int q1 = tid & 63;
    const int kg = tid >> 6;
    const int qg1 = qb * 64 + q1;
    // phase-2 mapping: ks = k half, qg = 2-query group, ds = 16-dim split
    const int ks   = tid >> 7;         // 0..1
    const int slot = tid & 127;
    const int qg   = slot >> 2;        // 0..31
    const int ds   = slot & 3;         // 0..3

    // query path params for phase 1: agree = fma(2p-1, pk, 1-p)
    float uq[TD], vq[TD];
    {
        const float* prow = g_P + (size_t)(b * TT + qg1) * PCOLS + h * TD;
        #pragma unroll
        for (int d = 0; d < TD; d++) {
            float p = prow[d];
            uq[d] = 2.f * p - 1.f;
            vq[d] = 1.f - p;
        }
    }

    float4 accA[4], accB[4];
    #pragma unroll
    for (int i = 0; i < 4; i++) {
        accA[i] = make_float4(0.f, 0.f, 0.f, 0.f);
        accB[i] = make_float4(0.f, 0.f, 0.f, 0.f);
    }
    float denA = 0.f, denB = 0.f;

    for (int kb = 0; kb <= qb; kb++) {
        const int k0 = kb * 64;

        // stage key paths transposed (5 x 64)
        for (int i = tid; i < TD * 64; i += 256) {
            int d = i >> 6, k = i & 63;
            kpT[d][k] = g_P[(size_t)(b * TT + k0 + k) * PCOLS + h * TD + d];
        }
        __syncthreads();

        // phase 1: each thread computes 16 (q,k) pairs once -> EsT[k][q]
        #pragma unroll
        for (int j = 0; j < 16; j++) {
            const int k = kg * 16 + j;
            float cp = 1.f, s = 0.f;
            #pragma unroll
            for (int d = 0; d < TD; d++) {
                float a = fmaf(uq[d], kpT[d][k], vq[d]);
                cp *= a;
                s  += cp;
            }
            float e = __expf(s * 0.2f);
            if (k0 + k > qg1) e = 0.f;          // causal mask
            buf[k * EST_STRIDE + q1] = e;
        }
        __syncthreads();

        // phase 2: this thread's k half, 2 queries x 16 dims, V via LDG
        const float* vbase = g_V + (size_t)(b * TT + k0 + ks * 32) * DM
                             + h * DH + ds * 16;
        #pragma unroll 4
        for (int kk2 = 0; kk2 < 32; kk2++) {
            const int kk = ks * 32 + kk2;
            const float2 e2 = *(const float2*)&buf[kk * EST_STRIDE + qg * 2];
            const float4* vr = (const float4*)(vbase + (size_t)kk2 * DM);
            float4 v0 = vr[0], v1 = vr[1], v2 = vr[2], v3 = vr[3];
            denA += e2.x; denB += e2.y;
            accA[0].x = fmaf(e2.x, v0.x, accA[0].x); accA[0].y = fmaf(e2.x, v0.y, accA[0].y);
            accA[0].z = fmaf(e2.x, v0.z, accA[0].z); accA[0].w = fmaf(e2.x, v0.w, accA[0].w);
            accA[1].x = fmaf(e2.x, v1.x, accA[1].x); accA[1].y = fmaf(e2.x, v1.y, accA[1].y);
            accA[1].z = fmaf(e2.x, v1.z, accA[1].z); accA[1].w = fmaf(e2.x, v1.w, accA[1].w);
            accA[2].x = fmaf(e2.x, v2.x, accA[2].x); accA[2].y = fmaf(e2.x, v2.y, accA[2].y);
            accA[2].z = fmaf(e2.x, v2.z, accA[2].z); accA[2].w = fmaf(e2.x, v2.w, accA[2].w);
            accA[3].x = fmaf(e2.x, v3.x, accA[3].x); accA[3].y = fmaf(e2.x, v3.y, accA[3].y);
            accA[3].z = fmaf(e2.x, v3.z, accA[3].z); accA[3].w = fmaf(e2.x, v3.w, accA[3].w);
            accB[0].x = fmaf(e2.y, v0.x, accB[0].x); accB[0].y = fmaf(e2.y, v0.y, accB[0].y);
            accB[0].z = fmaf(e2.y, v0.z, accB[0].z); accB[0].w = fmaf(e2.y, v0.w, accB[0].w);
            accB[1].x = fmaf(e2.y, v1.x, accB[1].x); accB[1].y = fmaf(e2.y, v1.y, accB[1].y);
            accB[1].z = fmaf(e2.y, v1.z, accB[1].z); accB[1].w = fmaf(e2.y, v1.w, accB[1].w);
            accB[2].x = fmaf(e2.y, v2.x, accB[2].x); accB[2].y = fmaf(e2.y, v2.y, accB[2].y);
            accB[2].z = fmaf(e2.y, v2.z, accB[2].z); accB[2].w = fmaf(e2.y, v2.w, accB[2].w);
            accB[3].x = fmaf(e2.y, v3.x, accB[3].x); accB[3].y = fmaf(e2.y, v3.y, accB[3].y);
            accB[3].z = fmaf(e2.y, v3.z, accB[3].z); accB[3].w = fmaf(e2.y, v3.w, accB[3].w);
        }
        __syncthreads();   // EsT consumed; safe for next tile (or reduction)
    }

    // ---- k-split reduction (once per block), reusing buf as scratch
    if (ks == 1) {
        float4* r = (float4*)&buf[slot * RED_STRIDE];
        r[0] = accA[0]; r[1] = accA[1]; r[2] = accA[2]; r[3] = accA[3];
        r[4] = accB[0]; r[5] = accB[1]; r[6] = accB[2]; r[7] = accB[3];
        buf[slot * RED_STRIDE + 32] = denA;
        buf[slot * RED_STRIDE + 33] = denB;
    }
    __syncthreads();
    if (ks == 0) {
        const float4* r = (const float4*)&buf[slot * RED_STRIDE];
        #pragma unroll
        for (int i = 0; i < 4; i++) {
            float4 ra = r[i], rb2 = r[4 + i];
            accA[i].x += ra.x;  accA[i].y += ra.y;  accA[i].z += ra.z;  accA[i].w += ra.w;
            accB[i].x += rb2.x; accB[i].y += rb2.y; accB[i].z += rb2.z; accB[i].w += rb2.w;
        }
        denA += buf[slot * RED_STRIDE + 32];
        denB += buf[slot * RED_STRIDE + 33];

        const float invA = 1.f / denA;
        const float invB = 1.f / denB;
        const int q = qb * 64 + qg * 2;
        float4* o0 = (float4*)(g_CTX + (size_t)(b * TT + q) * DM + h * DH + ds * 16);
        float4* o1 = (float4*)(g_CTX + (size_t)(b * TT + q + 1) * DM + h * DH + ds * 16);
        #pragma unroll
        for (int i = 0; i < 4; i++) {
            o0[i] = make_float4(accA[i].x * invA, accA[i].y * invA,
                                accA[i].z * invA, accA[i].w * invA);
            o1[i] = make_float4(accB[i].x * invB, accB[i].y * invB,
                                accB[i].z * invB, accB[i].w * invB);
        }
    }
}

// ---------------------------------------------------------------------------
// Launch
// ---------------------------------------------------------------------------
extern "C" void kernel_launch(void* const* d_in, const int* in_sizes, int n_in,
                              void* d_out, int out_size)
{
    const float* x  = (const float*)d_in[0];
    const float* Wp = (const float*)d_in[1];
    const float* bp = (const float*)d_in[2];
    const float* Wv = (const float*)d_in[3];
    const float* Wo = (const float*)d_in[4];
    float* out = (float*)d_out;

    // V = x@Wv (128 blocks) fused with P = sigmoid(x@Wp+bp) (16 blocks)
    gemm_vp_kernel<<<144, 256>>>(x, Wv, Wp, bp);

    // attention -> CTX
    attn_kernel<<<dim3(TT / 64, BATCH * NH), 256>>>();

    // out = CTX @ Wo
    gemm_o_kernel<<<dim3(DM / 128, (BATCH * TT) / 128), 256>>>(Wo, out);
}